// round 10
// baseline (speedup 1.0000x reference)
#include <cuda_runtime.h>
#include <cuda_fp16.h>

#define NN 8192
#define CC 16
#define KAUG 40          // halves per augmented row (24 used), 80B stride
#define UPAD 136
#define THREADS 256
#define ITILE 512        // i rows per CTA (m64 per warp)

// ---------------- device scratch ----------------
__device__ __align__(16) __half g_Aaug[NN * KAUG];
__device__ __align__(16) __half g_Baug[NN * KAUG];
__device__ __align__(16) __half g_UT[64 * CC * 128];   // [tile][c][j]

// smem layout (in halves)
#define SA  0
#define SB  20480
#define SU  25600
#define SMEM_HALVES 27776
#define SMEM_BYTES (SMEM_HALVES * 2)   // 55552 B

// ---------------- helpers ----------------
__device__ __forceinline__ unsigned s2u(const void* p) {
    return (unsigned)__cvta_generic_to_shared(p);
}
__device__ __forceinline__ unsigned cvt2h(float hi, float lo) {
    unsigned d; asm("cvt.rn.f16x2.f32 %0, %1, %2;" : "=r"(d) : "f"(hi), "f"(lo)); return d;
}
__device__ __forceinline__ unsigned ex2h(unsigned x) {
    unsigned y; asm("ex2.approx.f16x2 %0, %1;" : "=r"(y) : "r"(x)); return y;
}
__device__ __forceinline__ void ldsm4(unsigned& r0, unsigned& r1, unsigned& r2, unsigned& r3, unsigned a) {
    asm volatile("ldmatrix.sync.aligned.m8n8.x4.shared.b16 {%0,%1,%2,%3}, [%4];"
                 : "=r"(r0), "=r"(r1), "=r"(r2), "=r"(r3) : "r"(a));
}
__device__ __forceinline__ void mma16816(float* c, unsigned a0, unsigned a1, unsigned a2, unsigned a3,
                                         unsigned b0, unsigned b1) {
    asm volatile("mma.sync.aligned.m16n8k16.row.col.f32.f16.f16.f32 "
                 "{%0,%1,%2,%3}, {%4,%5,%6,%7}, {%8,%9}, {%0,%1,%2,%3};"
                 : "+f"(c[0]), "+f"(c[1]), "+f"(c[2]), "+f"(c[3])
                 : "r"(a0), "r"(a1), "r"(a2), "r"(a3), "r"(b0), "r"(b1));
}
__device__ __forceinline__ void cp16(unsigned saddr, const void* g) {
    asm volatile("cp.async.ca.shared.global [%0], [%1], 16;" :: "r"(saddr), "l"(g));
}
#define CP_COMMIT() asm volatile("cp.async.commit_group;" ::: "memory")

// ---------------- pre-kernel: 64 blocks x 256 threads, 128 rows each ----------------
__global__ __launch_bounds__(256) void lg_pre_kernel(const float* __restrict__ U,
                                                     const float* __restrict__ ref,
                                                     float* __restrict__ out) {
    __shared__ __half sUh[128 * 17];
    const int b = blockIdx.x;
    const int tid = threadIdx.x;

#pragma unroll
    for (int k = 0; k < 8; k++) {
        int idx = k * 256 + tid;
        float f = U[b * 2048 + idx];
        out[b * 2048 + idx] = -f;
        sUh[(idx >> 4) * 17 + (idx & 15)] = __float2half_rn(f);
    }
    __syncthreads();

    unsigned* gUTu = (unsigned*)g_UT;
#pragma unroll
    for (int k = 0; k < 4; k++) {
        int w = k * 256 + tid;
        int c  = w >> 6;
        int j2 = w & 63;
        __half h0 = sUh[(2 * j2) * 17 + c];
        __half h1 = sUh[(2 * j2 + 1) * 17 + c];
        unsigned v = (unsigned)__half_as_ushort(h0) | ((unsigned)__half_as_ushort(h1) << 16);
        gUTu[((size_t)b * 16 + c) * 64 + j2] = v;
    }

    if (tid < 128) {
        const int i = b * 128 + tid;
        const float SC = 1.2011224087864498f;  // sqrt(log2 e)
        float rs[5], ss = 0.f;
#pragma unroll
        for (int k = 0; k < 5; k++) { rs[k] = ref[i * 5 + k] * SC; ss += rs[k] * rs[k]; }
        float c = -0.5f * ss;
        unsigned short rh[5], rl[5], chh, cll;
#pragma unroll
        for (int k = 0; k < 5; k++) {
            __half hh = __float2half_rn(rs[k]);
            rh[k] = __half_as_ushort(hh);
            rl[k] = __half_as_ushort(__float2half_rn(rs[k] - __half2float(hh)));
        }
        {
            __half hc = __float2half_rn(c);
            chh = __half_as_ushort(hc);
            cll = __half_as_ushort(__float2half_rn(c - __half2float(hc)));
        }
        const unsigned short ONE = 0x3C00;
        unsigned short A[KAUG], B[KAUG];
#pragma unroll
        for (int k = 0; k < KAUG; k++) { A[k] = 0; B[k] = 0; }
        // A: k0-7=[rh,ch,1,0]  k8-15=[rl,cl,0,0]  k16-23=[rh,ch,1,0]
#pragma unroll
        for (int k = 0; k < 5; k++) { A[k] = rh[k]; A[8 + k] = rl[k]; A[16 + k] = rh[k]; }
        A[5] = chh; A[6] = ONE; A[13] = cll; A[21] = chh; A[22] = ONE;
        // B: k0-7=[rh,1,ch,0]  k8-15=same  k16-23=[rl,0,cl,0]
#pragma unroll
        for (int k = 0; k < 5; k++) { B[k] = rh[k]; B[8 + k] = rh[k]; B[16 + k] = rl[k]; }
        B[5] = ONE; B[6] = chh; B[13] = ONE; B[14] = chh; B[22] = cll;
        uint4* gA = (uint4*)(g_Aaug + (size_t)i * KAUG);
        uint4* gB = (uint4*)(g_Baug + (size_t)i * KAUG);
#pragma unroll
        for (int q = 0; q < 5; q++) {
            gA[q] = ((const uint4*)A)[q];
            gB[q] = ((const uint4*)B)[q];
        }
    }
}

// ---------------- main kernel: one (i512 x j128) tile per CTA, m64 per warp ----------------
__global__ __launch_bounds__(THREADS, 2) void lg_main_kernel(float* __restrict__ out) {
    extern __shared__ __align__(16) __half smem[];

    const int tid = threadIdx.x;
    const int w = tid >> 5;
    const int l = tid & 31;
    const int bx = blockIdx.x;   // i-tile (512 rows)
    const int by = blockIdx.y;   // j-tile (128 rows)

    const unsigned sAb = s2u(smem + SA);
    const unsigned sBb = s2u(smem + SB);
    const unsigned sUb = s2u(smem + SU);

    // ---- prologue: load A (512x80B), B (128x80B), U (16x256B) tiles ----
    {
        const char* gA = (const char*)(g_Aaug) + (size_t)bx * ITILE * KAUG * 2;
        for (int k = tid; k < 2560; k += THREADS) cp16(sAb + k * 16, gA + k * 16);
        const char* gB = (const char*)(g_Baug) + (size_t)by * 128 * KAUG * 2;
        for (int k = tid; k < 640; k += THREADS) cp16(sBb + k * 16, gB + k * 16);
        const char* gU = (const char*)(g_UT) + (size_t)by * CC * 256;
        for (int k = tid; k < 256; k += THREADS) {
            int row = k >> 4, q = k & 15;
            cp16(sUb + row * (UPAD * 2) + q * 16, gU + k * 16);
        }
        CP_COMMIT();
    }

    // lane address pieces
    const int lrowB = ((l >> 4) & 1) * 8 + (l & 7);
    const int lkB   = ((l >> 3) & 1) * 16;
    const int lrowA = ((l >> 3) & 1) * 8 + (l & 7);
    const int lkA   = ((l >> 4) & 1) * 16;

    const unsigned aAddr = sAb + (w * 64 + lrowA) * (KAUG * 2) + lkA;

    float o[4][2][4];
#pragma unroll
    for (int mb = 0; mb < 4; mb++)
#pragma unroll
        for (int nb = 0; nb < 2; nb++)
#pragma unroll
            for (int q = 0; q < 4; q++) o[mb][nb][q] = 0.f;

    asm volatile("cp.async.wait_group 0;" ::: "memory");
    __syncthreads();

    // A fragments: 4 m-blocks x 2 k-steps
    unsigned aF[4][2][4];
#pragma unroll
    for (int mb = 0; mb < 4; mb++) {
        const unsigned a0 = aAddr + mb * 16 * (KAUG * 2);
        ldsm4(aF[mb][0][0], aF[mb][0][1], aF[mb][0][2], aF[mb][0][3], a0);
        ldsm4(aF[mb][1][0], aF[mb][1][1], aF[mb][1][2], aF[mb][1][3], a0 + 32);
    }

#pragma unroll
    for (int p = 0; p < 8; p++) {
        const unsigned addrB = sBb + (p * 16 + lrowB) * (KAUG * 2) + lkB;
        unsigned b0, b1, b2, b3, b4, b5, b6, b7;
        ldsm4(b0, b1, b2, b3, addrB);        // k-step 0
        ldsm4(b4, b5, b6, b7, addrB + 32);   // k-step 1
        unsigned u0, u1, u2, u3;
        ldsm4(u0, u1, u2, u3, sUb + lrowB * (UPAD * 2) + p * 32 + lkB);

#pragma unroll
        for (int mb = 0; mb < 4; mb++) {
            float s0[4] = {0.f, 0.f, 0.f, 0.f};
            float s1[4] = {0.f, 0.f, 0.f, 0.f};
            mma16816(s0, aF[mb][0][0], aF[mb][0][1], aF[mb][0][2], aF[mb][0][3], b0, b1);
            mma16816(s1, aF[mb][0][0], aF[mb][0][1], aF[mb][0][2], aF[mb][0][3], b2, b3);
            mma16816(s0, aF[mb][1][0], aF[mb][1][1], aF[mb][1][2], aF[mb][1][3], b4, b5);
            mma16816(s1, aF[mb][1][0], aF[mb][1][1], aF[mb][1][2], aF[mb][1][3], b6, b7);
            unsigned w0 = ex2h(cvt2h(s0[1], s0[0]));
            unsigned w1 = ex2h(cvt2h(s0[3], s0[2]));
            unsigned w2 = ex2h(cvt2h(s1[1], s1[0]));
            unsigned w3 = ex2h(cvt2h(s1[3], s1[2]));
            mma16816(o[mb][0], w0, w1, w2, w3, u0, u1);
            mma16816(o[mb][1], w0, w1, w2, w3, u2, u3);
        }
    }

    // ---- epilogue ----
    const int g = l >> 2;
    const int tq = l & 3;
    const int ibase = bx * ITILE + w * 64 + g;
#pragma unroll
    for (int mb = 0; mb < 4; mb++) {
        const int i0 = ibase + mb * 16;
#pragma unroll
        for (int nb = 0; nb < 2; nb++) {
            const int col = nb * 8 + tq * 2;
            atomicAdd(&out[i0 * CC + col],           o[mb][nb][0]);
            atomicAdd(&out[i0 * CC + col + 1],       o[mb][nb][1]);
            atomicAdd(&out[(i0 + 8) * CC + col],     o[mb][nb][2]);
            atomicAdd(&out[(i0 + 8) * CC + col + 1], o[mb][nb][3]);
        }
    }
}

extern "C" void kernel_launch(void* const* d_in, const int* in_sizes, int n_in,
                              void* d_out, int out_size) {
    const float* U   = (const float*)d_in[0];
    const float* ref = (const float*)d_in[1];
    float* out = (float*)d_out;

    static int attrSet = 0;
    if (!attrSet) {
        cudaFuncSetAttribute(lg_main_kernel, cudaFuncAttributeMaxDynamicSharedMemorySize, SMEM_BYTES);
        attrSet = 1;
    }

    lg_pre_kernel<<<64, 256>>>(U, ref, out);

    dim3 grid(NN / ITILE, NN / 128);
    lg_main_kernel<<<grid, THREADS, SMEM_BYTES>>>(out);
}

// round 11
// speedup vs baseline: 1.1864x; 1.1864x over previous
#include <cuda_runtime.h>
#include <cuda_fp16.h>

#define NN 8192
#define CC 16
#define KAUG 24          // halves per augmented row (16 used), 48B stride (conflict-free)
#define UPAD 136
#define THREADS 256
#define ITILE 256

// ---------------- device scratch ----------------
__device__ __align__(16) __half g_Aaug[NN * KAUG];
__device__ __align__(16) __half g_Baug[NN * KAUG];
__device__ __align__(16) __half g_UT[64 * CC * 128];   // [tile][c][j]

// smem layout (in halves)
#define SA  0                      // 256*24 = 6144
#define SB  6144                   // 128*24 = 3072
#define SU  9216                   // 16*136 = 2176
#define SMEM_HALVES 11392
#define SMEM_BYTES (SMEM_HALVES * 2)   // 22784 B

// ---------------- helpers ----------------
__device__ __forceinline__ unsigned s2u(const void* p) {
    return (unsigned)__cvta_generic_to_shared(p);
}
__device__ __forceinline__ unsigned cvt2h(float hi, float lo) {
    unsigned d; asm("cvt.rn.f16x2.f32 %0, %1, %2;" : "=r"(d) : "f"(hi), "f"(lo)); return d;
}
__device__ __forceinline__ unsigned ex2h(unsigned x) {
    unsigned y; asm("ex2.approx.f16x2 %0, %1;" : "=r"(y) : "r"(x)); return y;
}
__device__ __forceinline__ void ldsm4(unsigned& r0, unsigned& r1, unsigned& r2, unsigned& r3, unsigned a) {
    asm volatile("ldmatrix.sync.aligned.m8n8.x4.shared.b16 {%0,%1,%2,%3}, [%4];"
                 : "=r"(r0), "=r"(r1), "=r"(r2), "=r"(r3) : "r"(a));
}
__device__ __forceinline__ void mma16816(float* c, unsigned a0, unsigned a1, unsigned a2, unsigned a3,
                                         unsigned b0, unsigned b1) {
    asm volatile("mma.sync.aligned.m16n8k16.row.col.f32.f16.f16.f32 "
                 "{%0,%1,%2,%3}, {%4,%5,%6,%7}, {%8,%9}, {%0,%1,%2,%3};"
                 : "+f"(c[0]), "+f"(c[1]), "+f"(c[2]), "+f"(c[3])
                 : "r"(a0), "r"(a1), "r"(a2), "r"(a3), "r"(b0), "r"(b1));
}
__device__ __forceinline__ void cp16(unsigned saddr, const void* g) {
    asm volatile("cp.async.ca.shared.global [%0], [%1], 16;" :: "r"(saddr), "l"(g));
}
#define CP_COMMIT() asm volatile("cp.async.commit_group;" ::: "memory")

// ---------------- pre-kernel: 64 blocks x 256 threads, 128 rows each ----------------
__global__ __launch_bounds__(256) void lg_pre_kernel(const float* __restrict__ U,
                                                     const float* __restrict__ ref,
                                                     float* __restrict__ out) {
    __shared__ __half sUh[128 * 17];
    const int b = blockIdx.x;
    const int tid = threadIdx.x;

#pragma unroll
    for (int k = 0; k < 8; k++) {
        int idx = k * 256 + tid;
        float f = U[b * 2048 + idx];
        out[b * 2048 + idx] = -f;
        sUh[(idx >> 4) * 17 + (idx & 15)] = __float2half_rn(f);
    }
    __syncthreads();

    unsigned* gUTu = (unsigned*)g_UT;
#pragma unroll
    for (int k = 0; k < 4; k++) {
        int w = k * 256 + tid;
        int c  = w >> 6;
        int j2 = w & 63;
        __half h0 = sUh[(2 * j2) * 17 + c];
        __half h1 = sUh[(2 * j2 + 1) * 17 + c];
        unsigned v = (unsigned)__half_as_ushort(h0) | ((unsigned)__half_as_ushort(h1) << 16);
        gUTu[((size_t)b * 16 + c) * 64 + j2] = v;
    }

    if (tid < 128) {
        const int i = b * 128 + tid;
        const float SC = 1.2011224087864498f;  // sqrt(log2 e)
        float rs[5], ss = 0.f;
#pragma unroll
        for (int k = 0; k < 5; k++) { rs[k] = ref[i * 5 + k] * SC; ss += rs[k] * rs[k]; }
        float c = -0.5f * ss;
        unsigned short rh[5], rl[5], chh, cll;
#pragma unroll
        for (int k = 0; k < 5; k++) {
            __half hh = __float2half_rn(rs[k]);
            rh[k] = __half_as_ushort(hh);
            rl[k] = __half_as_ushort(__float2half_rn(rs[k] - __half2float(hh)));
        }
        {
            __half hc = __float2half_rn(c);
            chh = __half_as_ushort(hc);
            cll = __half_as_ushort(__float2half_rn(c - __half2float(hc)));
        }
        const unsigned short ONE = 0x3C00;
        unsigned short A[KAUG], B[KAUG];
#pragma unroll
        for (int k = 0; k < KAUG; k++) { A[k] = 0; B[k] = 0; }
        // K=16 single-step pairing:
        // A: [rh(0-4), rl(5-9), chh(10), cll(11), 1(12), 1(13), 0, 0]
        // B: [rh(0-4), rh(5-9), 1(10),  1(11),  chh(12), cll(13), 0, 0]
        // logit = (rh+rl)_i . rh_j + c_i + c_j = rs_i . rh_j + c_i + c_j
#pragma unroll
        for (int k = 0; k < 5; k++) { A[k] = rh[k]; A[5 + k] = rl[k]; }
        A[10] = chh; A[11] = cll; A[12] = ONE; A[13] = ONE;
#pragma unroll
        for (int k = 0; k < 5; k++) { B[k] = rh[k]; B[5 + k] = rh[k]; }
        B[10] = ONE; B[11] = ONE; B[12] = chh; B[13] = cll;
        uint4* gA = (uint4*)(g_Aaug + (size_t)i * KAUG);
        uint4* gB = (uint4*)(g_Baug + (size_t)i * KAUG);
#pragma unroll
        for (int q = 0; q < 3; q++) {
            gA[q] = ((const uint4*)A)[q];
            gB[q] = ((const uint4*)B)[q];
        }
    }
}

// ---------------- main kernel: one (i256 x j128) tile per CTA, m32 per warp ----------------
__global__ __launch_bounds__(THREADS, 3) void lg_main_kernel(float* __restrict__ out) {
    extern __shared__ __align__(16) __half smem[];

    const int tid = threadIdx.x;
    const int w = tid >> 5;
    const int l = tid & 31;
    const int bx = blockIdx.x;   // i-tile (256 rows)
    const int by = blockIdx.y;   // j-tile (128 rows)

    const unsigned sAb = s2u(smem + SA);
    const unsigned sBb = s2u(smem + SB);
    const unsigned sUb = s2u(smem + SU);

    // ---- prologue: load A (256x48B), B (128x48B), U (16x256B) ----
    {
        const char* gA = (const char*)(g_Aaug) + (size_t)bx * ITILE * KAUG * 2;
        for (int k = tid; k < 768; k += THREADS) cp16(sAb + k * 16, gA + k * 16);
        const char* gB = (const char*)(g_Baug) + (size_t)by * 128 * KAUG * 2;
        for (int k = tid; k < 384; k += THREADS) cp16(sBb + k * 16, gB + k * 16);
        const char* gU = (const char*)(g_UT) + (size_t)by * CC * 256;
        for (int k = tid; k < 256; k += THREADS) {
            int row = k >> 4, q = k & 15;
            cp16(sUb + row * (UPAD * 2) + q * 16, gU + k * 16);
        }
        CP_COMMIT();
    }

    // lane address pieces
    const int lrowB = ((l >> 4) & 1) * 8 + (l & 7);
    const int lkB   = ((l >> 3) & 1) * 16;
    const int lrowA = ((l >> 3) & 1) * 8 + (l & 7);
    const int lkA   = ((l >> 4) & 1) * 16;

    const unsigned aAddr = sAb + (w * 32 + lrowA) * (KAUG * 2) + lkA;

    float o0[2][4], o1[2][4];
#pragma unroll
    for (int nb = 0; nb < 2; nb++)
#pragma unroll
        for (int q = 0; q < 4; q++) { o0[nb][q] = 0.f; o1[nb][q] = 0.f; }

    asm volatile("cp.async.wait_group 0;" ::: "memory");
    __syncthreads();

    // A fragments: 2 m-blocks, 1 k16 step each
    unsigned aF0[4], aF1[4];
    ldsm4(aF0[0], aF0[1], aF0[2], aF0[3], aAddr);
    ldsm4(aF1[0], aF1[1], aF1[2], aF1[3], aAddr + 16 * (KAUG * 2));

#pragma unroll
    for (int p = 0; p < 8; p++) {
        unsigned b0, b1, b2, b3;
        ldsm4(b0, b1, b2, b3, sBb + (p * 16 + lrowB) * (KAUG * 2) + lkB);
        unsigned u0, u1, u2, u3;
        ldsm4(u0, u1, u2, u3, sUb + lrowB * (UPAD * 2) + p * 32 + lkB);

        // m-block 0
        unsigned w00, w01, w02, w03;
        {
            float s0[4] = {0.f, 0.f, 0.f, 0.f};
            float s1[4] = {0.f, 0.f, 0.f, 0.f};
            mma16816(s0, aF0[0], aF0[1], aF0[2], aF0[3], b0, b1);
            mma16816(s1, aF0[0], aF0[1], aF0[2], aF0[3], b2, b3);
            w00 = ex2h(cvt2h(s0[1], s0[0]));
            w01 = ex2h(cvt2h(s0[3], s0[2]));
            w02 = ex2h(cvt2h(s1[1], s1[0]));
            w03 = ex2h(cvt2h(s1[3], s1[2]));
        }
        // m-block 1
        unsigned w10, w11, w12, w13;
        {
            float s0[4] = {0.f, 0.f, 0.f, 0.f};
            float s1[4] = {0.f, 0.f, 0.f, 0.f};
            mma16816(s0, aF1[0], aF1[1], aF1[2], aF1[3], b0, b1);
            mma16816(s1, aF1[0], aF1[1], aF1[2], aF1[3], b2, b3);
            w10 = ex2h(cvt2h(s0[1], s0[0]));
            w11 = ex2h(cvt2h(s0[3], s0[2]));
            w12 = ex2h(cvt2h(s1[1], s1[0]));
            w13 = ex2h(cvt2h(s1[3], s1[2]));
        }

        mma16816(o0[0], w00, w01, w02, w03, u0, u1);
        mma16816(o0[1], w00, w01, w02, w03, u2, u3);
        mma16816(o1[0], w10, w11, w12, w13, u0, u1);
        mma16816(o1[1], w10, w11, w12, w13, u2, u3);
    }

    // ---- epilogue ----
    const int g = l >> 2;
    const int tq = l & 3;
    const int i0 = bx * ITILE + w * 32 + g;
#pragma unroll
    for (int nb = 0; nb < 2; nb++) {
        const int col = nb * 8 + tq * 2;
        atomicAdd(&out[i0 * CC + col],            o0[nb][0]);
        atomicAdd(&out[i0 * CC + col + 1],        o0[nb][1]);
        atomicAdd(&out[(i0 + 8) * CC + col],      o0[nb][2]);
        atomicAdd(&out[(i0 + 8) * CC + col + 1],  o0[nb][3]);
        atomicAdd(&out[(i0 + 16) * CC + col],     o1[nb][0]);
        atomicAdd(&out[(i0 + 16) * CC + col + 1], o1[nb][1]);
        atomicAdd(&out[(i0 + 24) * CC + col],     o1[nb][2]);
        atomicAdd(&out[(i0 + 24) * CC + col + 1], o1[nb][3]);
    }
}

extern "C" void kernel_launch(void* const* d_in, const int* in_sizes, int n_in,
                              void* d_out, int out_size) {
    const float* U   = (const float*)d_in[0];
    const float* ref = (const float*)d_in[1];
    float* out = (float*)d_out;

    static int attrSet = 0;
    if (!attrSet) {
        cudaFuncSetAttribute(lg_main_kernel, cudaFuncAttributeMaxDynamicSharedMemorySize, SMEM_BYTES);
        attrSet = 1;
    }

    lg_pre_kernel<<<64, 256>>>(U, ref, out);

    dim3 grid(NN / ITILE, NN / 128);
    lg_main_kernel<<<grid, THREADS, SMEM_BYTES>>>(out);
}

// round 12
// speedup vs baseline: 1.2824x; 1.0809x over previous
#include <cuda_runtime.h>
#include <cuda_fp16.h>

#define NN 8192
#define CC 16
#define KAUG 24          // halves per augmented row (16 used), 48B stride (conflict-free)
#define UPAD 136
#define THREADS 256
#define ITILE 256

// ---------------- device scratch ----------------
__device__ __align__(16) __half g_Aaug[NN * KAUG];
__device__ __align__(16) __half g_Baug[NN * KAUG];
__device__ __align__(16) __half g_UT[64 * CC * 128];   // [tile][c][j]

// smem layout (in halves)
#define SA  0                      // 256*24 = 6144
#define SB  6144                   // 128*24 = 3072
#define SU  9216                   // 16*136 = 2176
#define SMEM_HALVES 11392
#define SMEM_BYTES (SMEM_HALVES * 2)   // 22784 B

// ---------------- helpers ----------------
__device__ __forceinline__ unsigned s2u(const void* p) {
    return (unsigned)__cvta_generic_to_shared(p);
}
__device__ __forceinline__ unsigned cvt2h(float hi, float lo) {
    unsigned d; asm("cvt.rn.f16x2.f32 %0, %1, %2;" : "=r"(d) : "f"(hi), "f"(lo)); return d;
}
__device__ __forceinline__ unsigned ex2h(unsigned x) {
    unsigned y; asm("ex2.approx.f16x2 %0, %1;" : "=r"(y) : "r"(x)); return y;
}
__device__ __forceinline__ void ldsm4(unsigned& r0, unsigned& r1, unsigned& r2, unsigned& r3, unsigned a) {
    asm volatile("ldmatrix.sync.aligned.m8n8.x4.shared.b16 {%0,%1,%2,%3}, [%4];"
                 : "=r"(r0), "=r"(r1), "=r"(r2), "=r"(r3) : "r"(a));
}
__device__ __forceinline__ void mma16816(float* c, unsigned a0, unsigned a1, unsigned a2, unsigned a3,
                                         unsigned b0, unsigned b1) {
    asm volatile("mma.sync.aligned.m16n8k16.row.col.f32.f16.f16.f32 "
                 "{%0,%1,%2,%3}, {%4,%5,%6,%7}, {%8,%9}, {%0,%1,%2,%3};"
                 : "+f"(c[0]), "+f"(c[1]), "+f"(c[2]), "+f"(c[3])
                 : "r"(a0), "r"(a1), "r"(a2), "r"(a3), "r"(b0), "r"(b1));
}
__device__ __forceinline__ void cp16(unsigned saddr, const void* g) {
    asm volatile("cp.async.ca.shared.global [%0], [%1], 16;" :: "r"(saddr), "l"(g));
}
#define CP_COMMIT() asm volatile("cp.async.commit_group;" ::: "memory")

// ---------------- pre-kernel: 64 blocks x 256 threads, 128 rows each ----------------
__global__ __launch_bounds__(256) void lg_pre_kernel(const float* __restrict__ U,
                                                     const float* __restrict__ ref,
                                                     float* __restrict__ out) {
    __shared__ __half sUh[128 * 17];
    const int b = blockIdx.x;
    const int tid = threadIdx.x;

#pragma unroll
    for (int k = 0; k < 8; k++) {
        int idx = k * 256 + tid;
        float f = U[b * 2048 + idx];
        out[b * 2048 + idx] = -f;
        sUh[(idx >> 4) * 17 + (idx & 15)] = __float2half_rn(f);
    }
    __syncthreads();

    unsigned* gUTu = (unsigned*)g_UT;
#pragma unroll
    for (int k = 0; k < 4; k++) {
        int w = k * 256 + tid;
        int c  = w >> 6;
        int j2 = w & 63;
        __half h0 = sUh[(2 * j2) * 17 + c];
        __half h1 = sUh[(2 * j2 + 1) * 17 + c];
        unsigned v = (unsigned)__half_as_ushort(h0) | ((unsigned)__half_as_ushort(h1) << 16);
        gUTu[((size_t)b * 16 + c) * 64 + j2] = v;
    }

    if (tid < 128) {
        const int i = b * 128 + tid;
        const float SC = 1.2011224087864498f;  // sqrt(log2 e)
        float rs[5], ss = 0.f;
#pragma unroll
        for (int k = 0; k < 5; k++) { rs[k] = ref[i * 5 + k] * SC; ss += rs[k] * rs[k]; }
        float c = -0.5f * ss;
        unsigned short rh[5], rl[5], chh, cll;
#pragma unroll
        for (int k = 0; k < 5; k++) {
            __half hh = __float2half_rn(rs[k]);
            rh[k] = __half_as_ushort(hh);
            rl[k] = __half_as_ushort(__float2half_rn(rs[k] - __half2float(hh)));
        }
        {
            __half hc = __float2half_rn(c);
            chh = __half_as_ushort(hc);
            cll = __half_as_ushort(__float2half_rn(c - __half2float(hc)));
        }
        const unsigned short ONE = 0x3C00;
        unsigned short A[KAUG], B[KAUG];
#pragma unroll
        for (int k = 0; k < KAUG; k++) { A[k] = 0; B[k] = 0; }
        // K=16 single-step pairing:
        // A: [rh(0-4), rl(5-9), chh(10), cll(11), 1(12), 1(13), 0, 0]
        // B: [rh(0-4), rh(5-9), 1(10),  1(11),  chh(12), cll(13), 0, 0]
        // logit = rs_i . rh_j + c_i + c_j
#pragma unroll
        for (int k = 0; k < 5; k++) { A[k] = rh[k]; A[5 + k] = rl[k]; }
        A[10] = chh; A[11] = cll; A[12] = ONE; A[13] = ONE;
#pragma unroll
        for (int k = 0; k < 5; k++) { B[k] = rh[k]; B[5 + k] = rh[k]; }
        B[10] = ONE; B[11] = ONE; B[12] = chh; B[13] = cll;
        uint4* gA = (uint4*)(g_Aaug + (size_t)i * KAUG);
        uint4* gB = (uint4*)(g_Baug + (size_t)i * KAUG);
#pragma unroll
        for (int q = 0; q < 3; q++) {
            gA[q] = ((const uint4*)A)[q];
            gB[q] = ((const uint4*)B)[q];
        }
    }
}

// ---------------- main kernel: one (i256 x j128) tile per CTA, m32 per warp, occ 4 ----------------
__global__ __launch_bounds__(THREADS, 4) void lg_main_kernel(float* __restrict__ out) {
    extern __shared__ __align__(16) __half smem[];

    const int tid = threadIdx.x;
    const int w = tid >> 5;
    const int l = tid & 31;
    const int bx = blockIdx.x;   // i-tile (256 rows)
    const int by = blockIdx.y;   // j-tile (128 rows)

    const unsigned sAb = s2u(smem + SA);
    const unsigned sBb = s2u(smem + SB);
    const unsigned sUb = s2u(smem + SU);

    // ---- prologue: load A (256x48B), B (128x48B), U (16x256B) ----
    {
        const char* gA = (const char*)(g_Aaug) + (size_t)bx * ITILE * KAUG * 2;
        for (int k = tid; k < 768; k += THREADS) cp16(sAb + k * 16, gA + k * 16);
        const char* gB = (const char*)(g_Baug) + (size_t)by * 128 * KAUG * 2;
        for (int k = tid; k < 384; k += THREADS) cp16(sBb + k * 16, gB + k * 16);
        const char* gU = (const char*)(g_UT) + (size_t)by * CC * 256;
        for (int k = tid; k < 256; k += THREADS) {
            int row = k >> 4, q = k & 15;
            cp16(sUb + row * (UPAD * 2) + q * 16, gU + k * 16);
        }
        CP_COMMIT();
    }

    // lane address pieces
    const int lrowB = ((l >> 4) & 1) * 8 + (l & 7);
    const int lkB   = ((l >> 3) & 1) * 16;
    const int lrowA = ((l >> 3) & 1) * 8 + (l & 7);
    const int lkA   = ((l >> 4) & 1) * 16;

    const unsigned aAddr = sAb + (w * 32 + lrowA) * (KAUG * 2) + lkA;

    float o0[2][4], o1[2][4];
#pragma unroll
    for (int nb = 0; nb < 2; nb++)
#pragma unroll
        for (int q = 0; q < 4; q++) { o0[nb][q] = 0.f; o1[nb][q] = 0.f; }

    asm volatile("cp.async.wait_group 0;" ::: "memory");
    __syncthreads();

    // A fragments: 2 m-blocks, 1 k16 step each
    unsigned aF0[4], aF1[4];
    ldsm4(aF0[0], aF0[1], aF0[2], aF0[3], aAddr);
    ldsm4(aF1[0], aF1[1], aF1[2], aF1[3], aAddr + 16 * (KAUG * 2));

#pragma unroll
    for (int p = 0; p < 8; p++) {
        unsigned b0, b1, b2, b3;
        ldsm4(b0, b1, b2, b3, sBb + (p * 16 + lrowB) * (KAUG * 2) + lkB);
        unsigned u0, u1, u2, u3;
        ldsm4(u0, u1, u2, u3, sUb + lrowB * (UPAD * 2) + p * 32 + lkB);

        // m-block 0
        unsigned w00, w01, w02, w03;
        {
            float s0[4] = {0.f, 0.f, 0.f, 0.f};
            float s1[4] = {0.f, 0.f, 0.f, 0.f};
            mma16816(s0, aF0[0], aF0[1], aF0[2], aF0[3], b0, b1);
            mma16816(s1, aF0[0], aF0[1], aF0[2], aF0[3], b2, b3);
            w00 = ex2h(cvt2h(s0[1], s0[0]));
            w01 = ex2h(cvt2h(s0[3], s0[2]));
            w02 = ex2h(cvt2h(s1[1], s1[0]));
            w03 = ex2h(cvt2h(s1[3], s1[2]));
        }
        // m-block 1
        unsigned w10, w11, w12, w13;
        {
            float s0[4] = {0.f, 0.f, 0.f, 0.f};
            float s1[4] = {0.f, 0.f, 0.f, 0.f};
            mma16816(s0, aF1[0], aF1[1], aF1[2], aF1[3], b0, b1);
            mma16816(s1, aF1[0], aF1[1], aF1[2], aF1[3], b2, b3);
            w10 = ex2h(cvt2h(s0[1], s0[0]));
            w11 = ex2h(cvt2h(s0[3], s0[2]));
            w12 = ex2h(cvt2h(s1[1], s1[0]));
            w13 = ex2h(cvt2h(s1[3], s1[2]));
        }

        mma16816(o0[0], w00, w01, w02, w03, u0, u1);
        mma16816(o0[1], w00, w01, w02, w03, u2, u3);
        mma16816(o1[0], w10, w11, w12, w13, u0, u1);
        mma16816(o1[1], w10, w11, w12, w13, u2, u3);
    }

    // ---- epilogue ----
    const int g = l >> 2;
    const int tq = l & 3;
    const int i0 = bx * ITILE + w * 32 + g;
#pragma unroll
    for (int nb = 0; nb < 2; nb++) {
        const int col = nb * 8 + tq * 2;
        atomicAdd(&out[i0 * CC + col],            o0[nb][0]);
        atomicAdd(&out[i0 * CC + col + 1],        o0[nb][1]);
        atomicAdd(&out[(i0 + 8) * CC + col],      o0[nb][2]);
        atomicAdd(&out[(i0 + 8) * CC + col + 1],  o0[nb][3]);
        atomicAdd(&out[(i0 + 16) * CC + col],     o1[nb][0]);
        atomicAdd(&out[(i0 + 16) * CC + col + 1], o1[nb][1]);
        atomicAdd(&out[(i0 + 24) * CC + col],     o1[nb][2]);
        atomicAdd(&out[(i0 + 24) * CC + col + 1], o1[nb][3]);
    }
}

extern "C" void kernel_launch(void* const* d_in, const int* in_sizes, int n_in,
                              void* d_out, int out_size) {
    const float* U   = (const float*)d_in[0];
    const float* ref = (const float*)d_in[1];
    float* out = (float*)d_out;

    static int attrSet = 0;
    if (!attrSet) {
        cudaFuncSetAttribute(lg_main_kernel, cudaFuncAttributeMaxDynamicSharedMemorySize, SMEM_BYTES);
        attrSet = 1;
    }

    lg_pre_kernel<<<64, 256>>>(U, ref, out);

    dim3 grid(NN / ITILE, NN / 128);
    lg_main_kernel<<<grid, THREADS, SMEM_BYTES>>>(out);
}

// round 13
// speedup vs baseline: 1.2883x; 1.0046x over previous
#include <cuda_runtime.h>
#include <cuda_fp16.h>

#define NN 8192
#define CC 16
#define KAUG 24          // halves per augmented row (16 used), 48B stride
#define UPAD 136
#define THREADS 256
#define ITILE 256
#define NTILES 4         // j-tiles of 128 per CTA -> grid 32 x 16 = 512 CTAs (single wave)

// ---------------- device scratch ----------------
__device__ __align__(16) __half g_Aaug[NN * KAUG];
__device__ __align__(16) __half g_Baug[NN * KAUG];
__device__ __align__(16) __half g_UT[64 * CC * 128];   // [tile][c][j]

// smem layout (in halves)
#define SA   0        // 256*24 = 6144
#define SB0  6144     // 128*24 = 3072
#define SB1  9216
#define SU0  12288    // 16*136 = 2176
#define SU1  14464
#define SMEM_HALVES 16640
#define SMEM_BYTES (SMEM_HALVES * 2)   // 33280 B

// ---------------- helpers ----------------
__device__ __forceinline__ unsigned s2u(const void* p) {
    return (unsigned)__cvta_generic_to_shared(p);
}
__device__ __forceinline__ unsigned cvt2h(float hi, float lo) {
    unsigned d; asm("cvt.rn.f16x2.f32 %0, %1, %2;" : "=r"(d) : "f"(hi), "f"(lo)); return d;
}
__device__ __forceinline__ unsigned ex2h(unsigned x) {
    unsigned y; asm("ex2.approx.f16x2 %0, %1;" : "=r"(y) : "r"(x)); return y;
}
__device__ __forceinline__ void ldsm4(unsigned& r0, unsigned& r1, unsigned& r2, unsigned& r3, unsigned a) {
    asm volatile("ldmatrix.sync.aligned.m8n8.x4.shared.b16 {%0,%1,%2,%3}, [%4];"
                 : "=r"(r0), "=r"(r1), "=r"(r2), "=r"(r3) : "r"(a));
}
__device__ __forceinline__ void mma16816(float* c, unsigned a0, unsigned a1, unsigned a2, unsigned a3,
                                         unsigned b0, unsigned b1) {
    asm volatile("mma.sync.aligned.m16n8k16.row.col.f32.f16.f16.f32 "
                 "{%0,%1,%2,%3}, {%4,%5,%6,%7}, {%8,%9}, {%0,%1,%2,%3};"
                 : "+f"(c[0]), "+f"(c[1]), "+f"(c[2]), "+f"(c[3])
                 : "r"(a0), "r"(a1), "r"(a2), "r"(a3), "r"(b0), "r"(b1));
}
__device__ __forceinline__ void cp16(unsigned saddr, const void* g) {
    asm volatile("cp.async.ca.shared.global [%0], [%1], 16;" :: "r"(saddr), "l"(g));
}
#define CP_COMMIT() asm volatile("cp.async.commit_group;" ::: "memory")

// ---------------- pre-kernel: 64 blocks x 256 threads, 128 rows each ----------------
__global__ __launch_bounds__(256) void lg_pre_kernel(const float* __restrict__ U,
                                                     const float* __restrict__ ref,
                                                     float* __restrict__ out) {
    __shared__ __half sUh[128 * 17];
    const int b = blockIdx.x;
    const int tid = threadIdx.x;

#pragma unroll
    for (int k = 0; k < 8; k++) {
        int idx = k * 256 + tid;
        float f = U[b * 2048 + idx];
        out[b * 2048 + idx] = -f;
        sUh[(idx >> 4) * 17 + (idx & 15)] = __float2half_rn(f);
    }
    __syncthreads();

    unsigned* gUTu = (unsigned*)g_UT;
#pragma unroll
    for (int k = 0; k < 4; k++) {
        int w = k * 256 + tid;
        int c  = w >> 6;
        int j2 = w & 63;
        __half h0 = sUh[(2 * j2) * 17 + c];
        __half h1 = sUh[(2 * j2 + 1) * 17 + c];
        unsigned v = (unsigned)__half_as_ushort(h0) | ((unsigned)__half_as_ushort(h1) << 16);
        gUTu[((size_t)b * 16 + c) * 64 + j2] = v;
    }

    if (tid < 128) {
        const int i = b * 128 + tid;
        const float SC = 1.2011224087864498f;  // sqrt(log2 e)
        float rs[5], ss = 0.f;
#pragma unroll
        for (int k = 0; k < 5; k++) { rs[k] = ref[i * 5 + k] * SC; ss += rs[k] * rs[k]; }
        float c = -0.5f * ss;
        unsigned short rh[5], rl[5], chh, cll;
#pragma unroll
        for (int k = 0; k < 5; k++) {
            __half hh = __float2half_rn(rs[k]);
            rh[k] = __half_as_ushort(hh);
            rl[k] = __half_as_ushort(__float2half_rn(rs[k] - __half2float(hh)));
        }
        {
            __half hc = __float2half_rn(c);
            chh = __half_as_ushort(hc);
            cll = __half_as_ushort(__float2half_rn(c - __half2float(hc)));
        }
        const unsigned short ONE = 0x3C00;
        unsigned short A[KAUG], B[KAUG];
#pragma unroll
        for (int k = 0; k < KAUG; k++) { A[k] = 0; B[k] = 0; }
        // K=16 single-step pairing:
        // A: [rh(0-4), rl(5-9), chh, cll, 1, 1, 0, 0]
        // B: [rh(0-4), rh(5-9), 1, 1, chh, cll, 0, 0]
        // logit = rs_i . rh_j + c_i + c_j
#pragma unroll
        for (int k = 0; k < 5; k++) { A[k] = rh[k]; A[5 + k] = rl[k]; }
        A[10] = chh; A[11] = cll; A[12] = ONE; A[13] = ONE;
#pragma unroll
        for (int k = 0; k < 5; k++) { B[k] = rh[k]; B[5 + k] = rh[k]; }
        B[10] = ONE; B[11] = ONE; B[12] = chh; B[13] = cll;
        uint4* gA = (uint4*)(g_Aaug + (size_t)i * KAUG);
        uint4* gB = (uint4*)(g_Baug + (size_t)i * KAUG);
#pragma unroll
        for (int q = 0; q < 3; q++) {
            gA[q] = ((const uint4*)A)[q];
            gB[q] = ((const uint4*)B)[q];
        }
    }
}

// ---------------- main kernel: (i256 x j512) per CTA, m32 per warp, occ 4 ----------------
__global__ __launch_bounds__(THREADS, 4) void lg_main_kernel(float* __restrict__ out) {
    extern __shared__ __align__(16) __half smem[];

    const int tid = threadIdx.x;
    const int w = tid >> 5;
    const int l = tid & 31;
    const int bx = blockIdx.x;   // i-tile (256 rows)
    const int by = blockIdx.y;   // j-group (4 tiles of 128)

    const unsigned sAb = s2u(smem + SA);
    const unsigned sBb0 = s2u(smem + SB0);
    const unsigned sBb1 = s2u(smem + SB1);
    const unsigned sUb0 = s2u(smem + SU0);
    const unsigned sUb1 = s2u(smem + SU1);

    // ---- prologue: A + first two B/U tiles ----
    {
        const char* gA = (const char*)(g_Aaug) + (size_t)bx * ITILE * KAUG * 2;
        for (int k = tid; k < 768; k += THREADS) cp16(sAb + k * 16, gA + k * 16);
        const int jt0 = by * NTILES;
        const char* gB = (const char*)(g_Baug) + (size_t)jt0 * 128 * KAUG * 2;
        for (int k = tid; k < 384; k += THREADS) cp16(sBb0 + k * 16, gB + k * 16);
        const char* gU = (const char*)(g_UT) + (size_t)jt0 * CC * 256;
        for (int k = tid; k < 256; k += THREADS) {
            int row = k >> 4, q = k & 15;
            cp16(sUb0 + row * (UPAD * 2) + q * 16, gU + k * 16);
        }
        CP_COMMIT();
        const char* gB1 = (const char*)(g_Baug) + (size_t)(jt0 + 1) * 128 * KAUG * 2;
        for (int k = tid; k < 384; k += THREADS) cp16(sBb1 + k * 16, gB1 + k * 16);
        const char* gU1 = (const char*)(g_UT) + (size_t)(jt0 + 1) * CC * 256;
        for (int k = tid; k < 256; k += THREADS) {
            int row = k >> 4, q = k & 15;
            cp16(sUb1 + row * (UPAD * 2) + q * 16, gU1 + k * 16);
        }
        CP_COMMIT();
    }

    // lane address pieces
    const int lrowB = ((l >> 4) & 1) * 8 + (l & 7);
    const int lkB   = ((l >> 3) & 1) * 16;
    const int lrowA = ((l >> 3) & 1) * 8 + (l & 7);
    const int lkA   = ((l >> 4) & 1) * 16;

    const unsigned aAddr = sAb + (w * 32 + lrowA) * (KAUG * 2) + lkA;

    float o0[2][4], o1[2][4];
#pragma unroll
    for (int nb = 0; nb < 2; nb++)
#pragma unroll
        for (int q = 0; q < 4; q++) { o0[nb][q] = 0.f; o1[nb][q] = 0.f; }

    unsigned aF0[4], aF1[4];
    bool aLoaded = false;

    for (int t = 0; t < NTILES; t++) {
        if (t == NTILES - 1) asm volatile("cp.async.wait_group 0;" ::: "memory");
        else                 asm volatile("cp.async.wait_group 1;" ::: "memory");
        __syncthreads();

        if (!aLoaded) {
            ldsm4(aF0[0], aF0[1], aF0[2], aF0[3], aAddr);
            ldsm4(aF1[0], aF1[1], aF1[2], aF1[3], aAddr + 16 * (KAUG * 2));
            aLoaded = true;
        }

        const unsigned bBase = (t & 1) ? sBb1 : sBb0;
        const unsigned uBase = (t & 1) ? sUb1 : sUb0;

#pragma unroll
        for (int p = 0; p < 8; p++) {
            unsigned b0, b1, b2, b3;
            ldsm4(b0, b1, b2, b3, bBase + (p * 16 + lrowB) * (KAUG * 2) + lkB);
            unsigned u0, u1, u2, u3;
            ldsm4(u0, u1, u2, u3, uBase + lrowB * (UPAD * 2) + p * 32 + lkB);

            // m-block 0
            unsigned w00, w01, w02, w03;
            {
                float s0[4] = {0.f, 0.f, 0.f, 0.f};
                float s1[4] = {0.f, 0.f, 0.f, 0.f};
                mma16816(s0, aF0[0], aF0[1], aF0[2], aF0[3], b0, b1);
                mma16816(s1, aF0[0], aF0[1], aF0[2], aF0[3], b2, b3);
                w00 = ex2h(cvt2h(s0[1], s0[0]));
                w01 = ex2h(cvt2h(s0[3], s0[2]));
                w02 = ex2h(cvt2h(s1[1], s1[0]));
                w03 = ex2h(cvt2h(s1[3], s1[2]));
            }
            // m-block 1
            unsigned w10, w11, w12, w13;
            {
                float s0[4] = {0.f, 0.f, 0.f, 0.f};
                float s1[4] = {0.f, 0.f, 0.f, 0.f};
                mma16816(s0, aF1[0], aF1[1], aF1[2], aF1[3], b0, b1);
                mma16816(s1, aF1[0], aF1[1], aF1[2], aF1[3], b2, b3);
                w10 = ex2h(cvt2h(s0[1], s0[0]));
                w11 = ex2h(cvt2h(s0[3], s0[2]));
                w12 = ex2h(cvt2h(s1[1], s1[0]));
                w13 = ex2h(cvt2h(s1[3], s1[2]));
            }

            mma16816(o0[0], w00, w01, w02, w03, u0, u1);
            mma16816(o0[1], w00, w01, w02, w03, u2, u3);
            mma16816(o1[0], w10, w11, w12, w13, u0, u1);
            mma16816(o1[1], w10, w11, w12, w13, u2, u3);
        }

        __syncthreads();

        // ---- prefetch tile t+2 into the just-freed buffer ----
        if (t + 2 < NTILES) {
            const int jt = by * NTILES + t + 2;
            const unsigned dB = (t & 1) ? sBb1 : sBb0;
            const unsigned dU = (t & 1) ? sUb1 : sUb0;
            const char* gB = (const char*)(g_Baug) + (size_t)jt * 128 * KAUG * 2;
            for (int k = tid; k < 384; k += THREADS) cp16(dB + k * 16, gB + k * 16);
            const char* gU = (const char*)(g_UT) + (size_t)jt * CC * 256;
            for (int k = tid; k < 256; k += THREADS) {
                int row = k >> 4, q = k & 15;
                cp16(dU + row * (UPAD * 2) + q * 16, gU + k * 16);
            }
            CP_COMMIT();
        } else {
            CP_COMMIT();
        }
    }

    // ---- epilogue (one atomic pass for 4 j-tiles) ----
    const int g = l >> 2;
    const int tq = l & 3;
    const int i0 = bx * ITILE + w * 32 + g;
#pragma unroll
    for (int nb = 0; nb < 2; nb++) {
        const int col = nb * 8 + tq * 2;
        atomicAdd(&out[i0 * CC + col],            o0[nb][0]);
        atomicAdd(&out[i0 * CC + col + 1],        o0[nb][1]);
        atomicAdd(&out[(i0 + 8) * CC + col],      o0[nb][2]);
        atomicAdd(&out[(i0 + 8) * CC + col + 1],  o0[nb][3]);
        atomicAdd(&out[(i0 + 16) * CC + col],     o1[nb][0]);
        atomicAdd(&out[(i0 + 16) * CC + col + 1], o1[nb][1]);
        atomicAdd(&out[(i0 + 24) * CC + col],     o1[nb][2]);
        atomicAdd(&out[(i0 + 24) * CC + col + 1], o1[nb][3]);
    }
}

extern "C" void kernel_launch(void* const* d_in, const int* in_sizes, int n_in,
                              void* d_out, int out_size) {
    const float* U   = (const float*)d_in[0];
    const float* ref = (const float*)d_in[1];
    float* out = (float*)d_out;

    static int attrSet = 0;
    if (!attrSet) {
        cudaFuncSetAttribute(lg_main_kernel, cudaFuncAttributeMaxDynamicSharedMemorySize, SMEM_BYTES);
        attrSet = 1;
    }

    lg_pre_kernel<<<64, 256>>>(U, ref, out);

    dim3 grid(NN / ITILE, NN / (128 * NTILES));
    lg_main_kernel<<<grid, THREADS, SMEM_BYTES>>>(out);
}